// round 1
// baseline (speedup 1.0000x reference)
#include <cuda_runtime.h>
#include <math.h>
#include <float.h>

#define BB 16
#define NN 1024
#define DD 5
#define RH 8
#define NWORDS 32            // 1024 bits / 32
#define ROWS (BB*NN)         // 16384

// ---------------- scratch (static device globals; no runtime alloc) --------
__device__ unsigned int   g_bits[ROWS*NWORDS];     // packed 1-hop adjacency (2 MB)
__device__ unsigned short g_idx[(size_t)ROWS*NN];  // compacted neighbor lists (32 MB)
__device__ int            g_cnt[ROWS];
__device__ float          g_q[ROWS*DD], g_k[ROWS*DD], g_v[ROWS*DD];
__device__ float          g_x[ROWS*DD];
__device__ int            g_fa, g_fb;              // dtype probe flags

// ---------------- dtype probe ----------------------------------------------
__global__ void k_init() {
    if (blockIdx.x == 0 && threadIdx.x == 0) { g_fa = 0; g_fb = 0; }
}

// Scan first 4MB of adj buffer (safe: buffer is >=16MB in every dtype case).
// uint8 bools: nonzero bytes at all offsets  -> fa=1, fb=1
// int32 bools: nonzero only at offset%4==0   -> fa=1, fb=0
// f32   bools: 1.0f = 00 00 80 3f            -> fa=0, fb=1
__global__ void k_detect(const uchar4* __restrict__ a, int n4) {
    int t = blockIdx.x * blockDim.x + threadIdx.x;
    int stride = gridDim.x * blockDim.x;
    unsigned fa = 0, fb = 0;
    for (int i = t; i < n4; i += stride) {
        uchar4 u = a[i];
        fa |= u.x;
        fb |= (unsigned)(u.y | u.z | u.w);
    }
    if (fa) g_fa = 1;
    if (fb) g_fb = 1;
}

// ---------------- pack adjacency into bitset --------------------------------
__global__ void k_pack(const uint4* __restrict__ a) {
    int t = blockIdx.x * blockDim.x + threadIdx.x;   // one 32-bit output word
    if (t >= ROWS * NWORDS) return;
    bool u8 = (g_fa && g_fb);
    unsigned bits = 0;
    if (u8) {
        // 32 one-byte elements = 32 bytes = 2 x uint4
        uint4 p0 = a[(size_t)t*2], p1 = a[(size_t)t*2 + 1];
        unsigned w[8] = {p0.x,p0.y,p0.z,p0.w,p1.x,p1.y,p1.z,p1.w};
        #pragma unroll
        for (int g = 0; g < 8; g++) {
            unsigned x = w[g];
            if (x & 0x000000FFu) bits |= 1u << (g*4+0);
            if (x & 0x0000FF00u) bits |= 1u << (g*4+1);
            if (x & 0x00FF0000u) bits |= 1u << (g*4+2);
            if (x & 0xFF000000u) bits |= 1u << (g*4+3);
        }
    } else {
        // 32 four-byte elements (int32 or f32: nonzero-word == true)
        #pragma unroll
        for (int g = 0; g < 8; g++) {
            uint4 p = a[(size_t)t*8 + g];
            if (p.x) bits |= 1u << (g*4+0);
            if (p.y) bits |= 1u << (g*4+1);
            if (p.z) bits |= 1u << (g*4+2);
            if (p.w) bits |= 1u << (g*4+3);
        }
    }
    g_bits[t] = bits;
}

// ---------------- 2-hop neighborhood + compaction (1 warp / row) -----------
__global__ void k_neigh() {
    int warp = (blockIdx.x * blockDim.x + threadIdx.x) >> 5;
    int lane = threadIdx.x & 31;
    if (warp >= ROWS) return;
    int b = warp / NN, i = warp % NN;

    unsigned self = g_bits[warp*NWORDS + lane];
    unsigned acc  = self;
    if ((i >> 5) == lane) acc |= 1u << (i & 31);     // eye

    int rowbase = b * NN;
    for (int w = 0; w < NWORDS; w++) {
        unsigned word = __shfl_sync(0xffffffffu, self, w);
        while (word) {
            int bit = __ffs(word) - 1; word &= word - 1;
            int j = w*32 + bit;
            acc |= g_bits[(rowbase + j)*NWORDS + lane];   // coalesced row OR
        }
    }
    // compact set bits -> index list
    int c = __popc(acc);
    int pre = c;
    #pragma unroll
    for (int off = 1; off < 32; off <<= 1) {
        int v = __shfl_up_sync(0xffffffffu, pre, off);
        if (lane >= off) pre += v;
    }
    int total = __shfl_sync(0xffffffffu, pre, 31);
    int pos = pre - c;
    unsigned m = acc;
    unsigned short* out = g_idx + (size_t)warp * NN;
    while (m) {
        int bit = __ffs(m) - 1; m &= m - 1;
        out[pos++] = (unsigned short)(lane*32 + bit);
    }
    if (lane == 0) g_cnt[warp] = total;
}

// ---------------- q,k,v projections (tiny) ----------------------------------
__global__ void k_qkv(const float* __restrict__ feats,
                      const float* __restrict__ Wq,
                      const float* __restrict__ Wk,
                      const float* __restrict__ Wv) {
    int t = blockIdx.x * blockDim.x + threadIdx.x;
    if (t >= ROWS) return;
    float f[DD];
    #pragma unroll
    for (int d = 0; d < DD; d++) f[d] = feats[t*DD + d];
    #pragma unroll
    for (int e = 0; e < DD; e++) {
        float q = 0.f, k = 0.f, v = 0.f;
        #pragma unroll
        for (int d = 0; d < DD; d++) {
            q = fmaf(f[d], Wq[d*DD + e], q);
            k = fmaf(f[d], Wk[d*DD + e], k);
            v = fmaf(f[d], Wv[d*DD + e], v);
        }
        g_q[t*DD + e] = q; g_k[t*DD + e] = k; g_v[t*DD + e] = v;
    }
}

// ---------------- sparse attention, online softmax (1 warp / row) ----------
__global__ void k_attn(const float* __restrict__ feats,
                       const float* __restrict__ coors,
                       const float* __restrict__ Wo,
                       const float* __restrict__ wr1,
                       const float* __restrict__ br1,
                       const float* __restrict__ wr2,
                       const float* __restrict__ br2) {
    int warp = (blockIdx.x * blockDim.x + threadIdx.x) >> 5;
    int lane = threadIdx.x & 31;
    if (warp >= ROWS) return;
    int b = warp / NN;

    float qs[DD];
    #pragma unroll
    for (int d = 0; d < DD; d++)
        qs[d] = g_q[warp*DD + d] * 0.44721359549995793f;   // 1/sqrt(5)
    float cx = coors[warp*3+0], cy = coors[warp*3+1], cz = coors[warp*3+2];

    float r1[RH], rb1[RH], r2[RH];
    #pragma unroll
    for (int h = 0; h < RH; h++) { r1[h] = wr1[h]; rb1[h] = br1[h]; r2[h] = wr2[h]; }
    float bc = br2[0];

    int cnt = g_cnt[warp];
    const unsigned short* idx = g_idx + (size_t)warp * NN;
    int kvbase = b * NN;

    float m = -FLT_MAX, s = 0.f;
    float acc[DD] = {0.f,0.f,0.f,0.f,0.f};

    for (int base = 0; base < cnt; base += 32) {
        int p = base + lane;
        if (p < cnt) {
            int j = kvbase + (int)idx[p];
            const float* kj = g_k + (size_t)j*DD;
            float sc = bc;
            #pragma unroll
            for (int d = 0; d < DD; d++) sc = fmaf(qs[d], kj[d], sc);
            float dx = cx - coors[j*3+0];
            float dy = cy - coors[j*3+1];
            float dz = cz - coors[j*3+2];
            float dist = sqrtf(fmaf(dx,dx, fmaf(dy,dy, fmaf(dz,dz, 1e-8f))));
            #pragma unroll
            for (int h = 0; h < RH; h++) {
                float t = fmaf(dist, r1[h], rb1[h]);
                sc = fmaf(fmaxf(t, 0.f), r2[h], sc);
            }
            float mn   = fmaxf(m, sc);
            float cold = __expf(m - mn);
            float e    = __expf(sc - mn);
            s = fmaf(s, cold, e);
            const float* vj = g_v + (size_t)j*DD;
            #pragma unroll
            for (int d = 0; d < DD; d++) acc[d] = fmaf(acc[d], cold, e * vj[d]);
            m = mn;
        }
    }
    // warp-level softmax-state merge
    #pragma unroll
    for (int off = 16; off; off >>= 1) {
        float m2 = __shfl_xor_sync(0xffffffffu, m, off);
        float s2 = __shfl_xor_sync(0xffffffffu, s, off);
        float a2[DD];
        #pragma unroll
        for (int d = 0; d < DD; d++) a2[d] = __shfl_xor_sync(0xffffffffu, acc[d], off);
        float mn = fmaxf(m, m2);
        float c1 = __expf(m - mn), c2 = __expf(m2 - mn);
        s = s*c1 + s2*c2;
        #pragma unroll
        for (int d = 0; d < DD; d++) acc[d] = acc[d]*c1 + a2[d]*c2;
        m = mn;
    }
    if (lane == 0) {
        float inv = 1.f / s;
        float agg[DD];
        #pragma unroll
        for (int d = 0; d < DD; d++) agg[d] = acc[d] * inv;
        #pragma unroll
        for (int e = 0; e < DD; e++) {
            float o = feats[warp*DD + e];
            #pragma unroll
            for (int d = 0; d < DD; d++) o = fmaf(agg[d], Wo[d*DD + e], o);
            g_x[warp*DD + e] = o;
        }
    }
}

// ---------------- mean-pool + MLP head (1 block / batch) --------------------
__global__ void k_pool(const float* __restrict__ w1, const float* __restrict__ b1,
                       const float* __restrict__ w2, const float* __restrict__ b2,
                       float* __restrict__ out) {
    int b = blockIdx.x;
    int t = threadIdx.x;              // 256 threads
    __shared__ float red[DD*256];
    __shared__ float sp[DD];
    __shared__ float sh[128];

    float loc[DD] = {0.f,0.f,0.f,0.f,0.f};
    for (int i = t; i < NN; i += 256) {
        const float* x = g_x + (size_t)(b*NN + i)*DD;
        #pragma unroll
        for (int d = 0; d < DD; d++) loc[d] += x[d];
    }
    #pragma unroll
    for (int d = 0; d < DD; d++) red[d*256 + t] = loc[d];
    __syncthreads();
    if (t < DD) {
        float s = 0.f;
        for (int k = 0; k < 256; k++) s += red[t*256 + k];
        sp[t] = s * (1.0f/NN);
    }
    __syncthreads();
    if (t < 128) {
        float h = b1[t];
        #pragma unroll
        for (int d = 0; d < DD; d++) h = fmaf(sp[d], w1[d*128 + t], h);
        sh[t] = fmaxf(h, 0.f);
    }
    __syncthreads();
    if (t < 3) {
        float o = b2[t];
        for (int h = 0; h < 128; h++) o = fmaf(sh[h], w2[h*3 + t], o);
        out[b*3 + t] = o;
    }
}

// ---------------- launcher ---------------------------------------------------
extern "C" void kernel_launch(void* const* d_in, const int* in_sizes, int n_in,
                              void* d_out, int out_size) {
    const float* feats = (const float*)d_in[0];
    const float* coors = (const float*)d_in[1];
    const void*  adj   = d_in[2];
    const float* Wq    = (const float*)d_in[3];
    const float* Wk    = (const float*)d_in[4];
    const float* Wv    = (const float*)d_in[5];
    const float* Wo    = (const float*)d_in[6];
    const float* wr1   = (const float*)d_in[7];
    const float* br1   = (const float*)d_in[8];
    const float* wr2   = (const float*)d_in[9];
    const float* br2   = (const float*)d_in[10];
    const float* w1    = (const float*)d_in[11];
    const float* b1    = (const float*)d_in[12];
    const float* w2    = (const float*)d_in[13];
    const float* b2    = (const float*)d_in[14];
    float* out = (float*)d_out;

    k_init<<<1, 32>>>();
    // probe first 4MB (1M uchar4) of adj buffer
    k_detect<<<512, 256>>>((const uchar4*)adj, (4<<20)/4);
    k_pack<<<(ROWS*NWORDS + 255)/256, 256>>>((const uint4*)adj);
    k_qkv<<<(ROWS + 255)/256, 256>>>(feats, Wq, Wk, Wv);
    k_neigh<<<(ROWS*32 + 255)/256, 256>>>();
    k_attn<<<(ROWS*32 + 255)/256, 256>>>(feats, coors, Wo, wr1, br1, wr2, br2);
    k_pool<<<BB, 256>>>(w1, b1, w2, b2, out);
}

// round 2
// speedup vs baseline: 1.3040x; 1.3040x over previous
#include <cuda_runtime.h>
#include <math.h>
#include <float.h>

#define BB 16
#define NN 1024
#define DD 5
#define RH 8
#define NWORDS 32            // 1024 bits / 32
#define ROWS (BB*NN)         // 16384
#define PACK_BLOCKS ((ROWS*NWORDS)/256)   // 2048
#define REC_BLOCKS  (ROWS/256)            // 64

// ---------------- scratch (static device globals; no runtime alloc) --------
__device__ unsigned int   g_bits[ROWS*NWORDS];     // packed 1-hop adjacency (2 MB)
__device__ unsigned short g_idx[(size_t)ROWS*NN];  // compacted neighbor lists (32 MB)
__device__ int            g_cnt[ROWS];
__device__ float4         g_rec[ROWS*4];           // per-node: k(5) v(5) coors(3) pad
__device__ float          g_q[ROWS*DD];            // pre-scaled q
__device__ float          g_x[ROWS*DD];
__device__ int            g_fa, g_fb;              // dtype probe flags (zero-init, monotonic)

// ---------------- dtype probe ----------------------------------------------
// uint8 bools: nonzero bytes at all offsets  -> fa=1, fb=1
// int32 bools: nonzero only at offset%4==0   -> fa=1, fb=0
// f32   bools: 1.0f = 00 00 80 3f            -> fa=0, fb=1
// Flags start zero (static init) and only ever OR in the same values on
// replays -> deterministic; no init kernel needed.
__global__ void k_detect(const uchar4* __restrict__ a, int n4) {
    int t = blockIdx.x * blockDim.x + threadIdx.x;
    int stride = gridDim.x * blockDim.x;
    unsigned fa = 0, fb = 0;
    for (int i = t; i < n4; i += stride) {
        uchar4 u = a[i];
        fa |= u.x;
        fb |= (unsigned)(u.y | u.z | u.w);
    }
    if (fa) g_fa = 1;
    if (fb) g_fb = 1;
}

// ---------------- pack adjacency into bitset + build node records ----------
__global__ void k_pack_rec(const uint4* __restrict__ a,
                           const float* __restrict__ feats,
                           const float* __restrict__ coors,
                           const float* __restrict__ Wq,
                           const float* __restrict__ Wk,
                           const float* __restrict__ Wv) {
    if (blockIdx.x < PACK_BLOCKS) {
        int t = blockIdx.x * blockDim.x + threadIdx.x;   // one 32-bit output word
        bool u8 = (g_fa && g_fb);
        unsigned bits = 0;
        if (u8) {
            uint4 p0 = a[(size_t)t*2], p1 = a[(size_t)t*2 + 1];
            unsigned w[8] = {p0.x,p0.y,p0.z,p0.w,p1.x,p1.y,p1.z,p1.w};
            #pragma unroll
            for (int g = 0; g < 8; g++) {
                unsigned x = w[g];
                if (x & 0x000000FFu) bits |= 1u << (g*4+0);
                if (x & 0x0000FF00u) bits |= 1u << (g*4+1);
                if (x & 0x00FF0000u) bits |= 1u << (g*4+2);
                if (x & 0xFF000000u) bits |= 1u << (g*4+3);
            }
        } else {
            #pragma unroll
            for (int g = 0; g < 8; g++) {
                uint4 p = a[(size_t)t*8 + g];
                if (p.x) bits |= 1u << (g*4+0);
                if (p.y) bits |= 1u << (g*4+1);
                if (p.z) bits |= 1u << (g*4+2);
                if (p.w) bits |= 1u << (g*4+3);
            }
        }
        g_bits[t] = bits;
    } else {
        int t = (blockIdx.x - PACK_BLOCKS) * blockDim.x + threadIdx.x;  // node
        float f[DD];
        #pragma unroll
        for (int d = 0; d < DD; d++) f[d] = feats[t*DD + d];
        float q[DD], k[DD], v[DD];
        #pragma unroll
        for (int e = 0; e < DD; e++) {
            float qq = 0.f, kk = 0.f, vv = 0.f;
            #pragma unroll
            for (int d = 0; d < DD; d++) {
                qq = fmaf(f[d], __ldg(&Wq[d*DD + e]), qq);
                kk = fmaf(f[d], __ldg(&Wk[d*DD + e]), kk);
                vv = fmaf(f[d], __ldg(&Wv[d*DD + e]), vv);
            }
            q[e] = qq; k[e] = kk; v[e] = vv;
        }
        #pragma unroll
        for (int e = 0; e < DD; e++)
            g_q[t*DD + e] = q[e] * 0.44721359549995793f;   // 1/sqrt(5)
        float c0 = coors[t*3+0], c1 = coors[t*3+1], c2 = coors[t*3+2];
        g_rec[t*4+0] = make_float4(k[0], k[1], k[2], k[3]);
        g_rec[t*4+1] = make_float4(k[4], v[0], v[1], v[2]);
        g_rec[t*4+2] = make_float4(v[3], v[4], c0, c1);
        g_rec[t*4+3] = make_float4(c2, 0.f, 0.f, 0.f);
    }
}

// ---------------- 2-hop neighborhood + compaction (1 warp / row) -----------
__global__ void k_neigh() {
    int warp = (blockIdx.x * blockDim.x + threadIdx.x) >> 5;
    int lane = threadIdx.x & 31;
    if (warp >= ROWS) return;
    int b = warp / NN, i = warp % NN;

    unsigned self = g_bits[warp*NWORDS + lane];
    unsigned acc  = self;
    if ((i >> 5) == lane) acc |= 1u << (i & 31);     // eye

    int rowbase = b * NN;
    for (int w = 0; w < NWORDS; w++) {
        unsigned word = __shfl_sync(0xffffffffu, self, w);
        while (word) {
            int bit = __ffs(word) - 1; word &= word - 1;
            int j = w*32 + bit;
            acc |= g_bits[(rowbase + j)*NWORDS + lane];   // coalesced row OR
        }
    }
    // compact set bits -> index list
    int c = __popc(acc);
    int pre = c;
    #pragma unroll
    for (int off = 1; off < 32; off <<= 1) {
        int v = __shfl_up_sync(0xffffffffu, pre, off);
        if (lane >= off) pre += v;
    }
    int total = __shfl_sync(0xffffffffu, pre, 31);
    int pos = pre - c;
    unsigned m = acc;
    unsigned short* out = g_idx + (size_t)warp * NN;
    while (m) {
        int bit = __ffs(m) - 1; m &= m - 1;
        out[pos++] = (unsigned short)(lane*32 + bit);
    }
    if (lane == 0) g_cnt[warp] = total;
}

// ---------------- sparse attention, SMEM-staged gather ----------------------
// 16 CTAs per batch, 256 threads (8 warps), 8 rows per warp.
// Per-batch record table (64KB) staged in dynamic smem, XOR-swizzled so
// random-node float4 gathers spread over all eight 16B bank groups.
__global__ void k_attn(const float* __restrict__ feats,
                       const float* __restrict__ Wo,
                       const float* __restrict__ wr1,
                       const float* __restrict__ br1,
                       const float* __restrict__ wr2,
                       const float* __restrict__ br2) {
    extern __shared__ float4 srec[];     // NN*4 float4 = 64KB
    int b   = blockIdx.x >> 4;
    int seg = blockIdx.x & 15;

    const float4* src = g_rec + (size_t)b * NN * 4;
    for (int i = threadIdx.x; i < NN*4; i += blockDim.x) {
        int j = i >> 2, q = i & 3;
        srec[(j << 2) | ((q ^ j) & 3)] = src[i];
    }
    __syncthreads();

    int lane = threadIdx.x & 31, warp = threadIdx.x >> 5;

    float r1[RH], rb1[RH], r2[RH];
    #pragma unroll
    for (int h = 0; h < RH; h++) {
        r1[h] = __ldg(&wr1[h]); rb1[h] = __ldg(&br1[h]); r2[h] = __ldg(&wr2[h]);
    }
    float bc = __ldg(&br2[0]);

    #pragma unroll 1
    for (int r = 0; r < 8; r++) {
        int i   = seg * 64 + warp * 8 + r;    // row within batch
        int row = b * NN + i;

        float q0 = g_q[row*DD+0], q1 = g_q[row*DD+1], q2 = g_q[row*DD+2];
        float q3 = g_q[row*DD+3], q4 = g_q[row*DD+4];
        float4 fi2 = srec[(i << 2) | ((2 ^ i) & 3)];
        float  cx = fi2.z, cy = fi2.w;
        float  cz = srec[(i << 2) | ((3 ^ i) & 3)].x;

        int cnt = g_cnt[row];
        const unsigned short* idx = g_idx + (size_t)row * NN;

        float m = -FLT_MAX, s = 0.f;
        float a0 = 0.f, a1 = 0.f, a2 = 0.f, a3 = 0.f, a4 = 0.f;

        for (int base = 0; base < cnt; base += 32) {
            int p = base + lane;
            if (p < cnt) {
                int j = (int)idx[p];
                float4 h0 = srec[(j << 2) | ( j      & 3)];
                float4 h1 = srec[(j << 2) | ((1 ^ j) & 3)];
                float4 h2 = srec[(j << 2) | ((2 ^ j) & 3)];
                float  hz = srec[(j << 2) | ((3 ^ j) & 3)].x;

                float sc = bc;
                sc = fmaf(q0, h0.x, sc); sc = fmaf(q1, h0.y, sc);
                sc = fmaf(q2, h0.z, sc); sc = fmaf(q3, h0.w, sc);
                sc = fmaf(q4, h1.x, sc);
                float dx = cx - h2.z, dy = cy - h2.w, dz = cz - hz;
                float dist = sqrtf(fmaf(dx,dx, fmaf(dy,dy, fmaf(dz,dz, 1e-8f))));
                #pragma unroll
                for (int h = 0; h < RH; h++) {
                    float t = fmaf(dist, r1[h], rb1[h]);
                    sc = fmaf(fmaxf(t, 0.f), r2[h], sc);
                }
                float mn   = fmaxf(m, sc);
                float cold = __expf(m - mn);
                float e    = __expf(sc - mn);
                s  = fmaf(s, cold, e);
                a0 = fmaf(a0, cold, e * h1.y);
                a1 = fmaf(a1, cold, e * h1.z);
                a2 = fmaf(a2, cold, e * h1.w);
                a3 = fmaf(a3, cold, e * h2.x);
                a4 = fmaf(a4, cold, e * h2.y);
                m = mn;
            }
        }
        // warp-level softmax-state merge
        #pragma unroll
        for (int off = 16; off; off >>= 1) {
            float m2 = __shfl_xor_sync(0xffffffffu, m, off);
            float s2 = __shfl_xor_sync(0xffffffffu, s, off);
            float b0 = __shfl_xor_sync(0xffffffffu, a0, off);
            float b1 = __shfl_xor_sync(0xffffffffu, a1, off);
            float b2 = __shfl_xor_sync(0xffffffffu, a2, off);
            float b3 = __shfl_xor_sync(0xffffffffu, a3, off);
            float b4 = __shfl_xor_sync(0xffffffffu, a4, off);
            float mn = fmaxf(m, m2);
            float c1 = __expf(m - mn), c2 = __expf(m2 - mn);
            s  = s*c1  + s2*c2;
            a0 = a0*c1 + b0*c2;
            a1 = a1*c1 + b1*c2;
            a2 = a2*c1 + b2*c2;
            a3 = a3*c1 + b3*c2;
            a4 = a4*c1 + b4*c2;
            m = mn;
        }
        if (lane == 0) {
            float inv = 1.f / s;
            float agg[DD] = {a0*inv, a1*inv, a2*inv, a3*inv, a4*inv};
            #pragma unroll
            for (int e = 0; e < DD; e++) {
                float o = feats[row*DD + e];
                #pragma unroll
                for (int d = 0; d < DD; d++) o = fmaf(agg[d], __ldg(&Wo[d*DD + e]), o);
                g_x[row*DD + e] = o;
            }
        }
    }
}

// ---------------- mean-pool + MLP head (1 block / batch) --------------------
__global__ void k_pool(const float* __restrict__ w1, const float* __restrict__ b1,
                       const float* __restrict__ w2, const float* __restrict__ b2,
                       float* __restrict__ out) {
    int b = blockIdx.x;
    int t = threadIdx.x;              // 256 threads
    __shared__ float red[DD*256];
    __shared__ float sp[DD];
    __shared__ float sh[128];

    float loc[DD] = {0.f,0.f,0.f,0.f,0.f};
    for (int i = t; i < NN; i += 256) {
        const float* x = g_x + (size_t)(b*NN + i)*DD;
        #pragma unroll
        for (int d = 0; d < DD; d++) loc[d] += x[d];
    }
    #pragma unroll
    for (int d = 0; d < DD; d++) red[d*256 + t] = loc[d];
    __syncthreads();
    if (t < DD) {
        float s = 0.f;
        for (int k = 0; k < 256; k++) s += red[t*256 + k];
        sp[t] = s * (1.0f/NN);
    }
    __syncthreads();
    if (t < 128) {
        float h = b1[t];
        #pragma unroll
        for (int d = 0; d < DD; d++) h = fmaf(sp[d], w1[d*128 + t], h);
        sh[t] = fmaxf(h, 0.f);
    }
    __syncthreads();
    if (t < 3) {
        float o = b2[t];
        for (int h = 0; h < 128; h++) o = fmaf(sh[h], w2[h*3 + t], o);
        out[b*3 + t] = o;
    }
}

// ---------------- launcher ---------------------------------------------------
extern "C" void kernel_launch(void* const* d_in, const int* in_sizes, int n_in,
                              void* d_out, int out_size) {
    const float* feats = (const float*)d_in[0];
    const float* coors = (const float*)d_in[1];
    const void*  adj   = d_in[2];
    const float* Wq    = (const float*)d_in[3];
    const float* Wk    = (const float*)d_in[4];
    const float* Wv    = (const float*)d_in[5];
    const float* Wo    = (const float*)d_in[6];
    const float* wr1   = (const float*)d_in[7];
    const float* br1   = (const float*)d_in[8];
    const float* wr2   = (const float*)d_in[9];
    const float* br2   = (const float*)d_in[10];
    const float* w1    = (const float*)d_in[11];
    const float* b1    = (const float*)d_in[12];
    const float* w2    = (const float*)d_in[13];
    const float* b2    = (const float*)d_in[14];
    float* out = (float*)d_out;

    cudaFuncSetAttribute(k_attn, cudaFuncAttributeMaxDynamicSharedMemorySize, 65536);

    k_detect<<<512, 256>>>((const uchar4*)adj, (4<<20)/4);
    k_pack_rec<<<PACK_BLOCKS + REC_BLOCKS, 256>>>((const uint4*)adj, feats, coors, Wq, Wk, Wv);
    k_neigh<<<(ROWS*32 + 255)/256, 256>>>();
    k_attn<<<BB*16, 256, 65536>>>(feats, Wo, wr1, br1, wr2, br2);
    k_pool<<<BB, 256>>>(w1, b1, w2, b2, out);
}

// round 3
// speedup vs baseline: 1.6390x; 1.2570x over previous
#include <cuda_runtime.h>
#include <math.h>
#include <float.h>

#define BB 16
#define NN 1024
#define DD 5
#define RH 8
#define NWORDS 32            // 1024 bits / 32
#define ROWS (BB*NN)         // 16384
#define PACK_BLOCKS ((ROWS*NWORDS)/256)   // 2048
#define REC_BLOCKS  (ROWS/256)            // 64

// ---------------- scratch (static device globals; no runtime alloc) --------
__device__ unsigned int   g_bits[ROWS*NWORDS];     // packed 1-hop adjacency (2 MB)
__device__ unsigned short g_idx[(size_t)ROWS*NN];  // compacted neighbor lists (32 MB)
__device__ int            g_cnt[ROWS];
__device__ float4         g_t0[ROWS];              // k0..k3
__device__ float4         g_t1[ROWS];              // cx,cy,cz,k4
__device__ float4         g_t2[ROWS];              // v0..v3
__device__ float          g_t3[ROWS];              // v4
__device__ float          g_q[ROWS*DD];            // pre-scaled q
__device__ float          g_x[ROWS*DD];
__device__ int            g_fa, g_fb;              // dtype probe flags (zero-init, monotonic)
__device__ int            g_simple;                // rbias is linear in dist
__device__ float          g_C, g_bcShift;          // rbias slope, b2 - 30 shift

// ---------------- dtype probe ----------------------------------------------
// uint8 bools: nonzero bytes at all offsets  -> fa=1, fb=1
// int32 bools: nonzero only at offset%4==0   -> fa=1, fb=0
// f32   bools: 1.0f = 00 00 80 3f            -> fa=0, fb=1
__global__ void k_detect(const uchar4* __restrict__ a, int n4) {
    int t = blockIdx.x * blockDim.x + threadIdx.x;
    int stride = gridDim.x * blockDim.x;
    unsigned fa = 0, fb = 0;
    for (int i = t; i < n4; i += stride) {
        uchar4 u = a[i];
        fa |= u.x;
        fb |= (unsigned)(u.y | u.z | u.w);
    }
    if (fa) g_fa = 1;
    if (fb) g_fb = 1;
}

// ------- pack adjacency bitset + build node tables + radial coeffs ---------
__global__ void k_pack_rec(const uint4* __restrict__ a,
                           const float* __restrict__ feats,
                           const float* __restrict__ coors,
                           const float* __restrict__ Wq,
                           const float* __restrict__ Wk,
                           const float* __restrict__ Wv,
                           const float* __restrict__ wr1,
                           const float* __restrict__ br1,
                           const float* __restrict__ wr2,
                           const float* __restrict__ br2) {
    if (blockIdx.x < PACK_BLOCKS) {
        int t = blockIdx.x * blockDim.x + threadIdx.x;   // one 32-bit output word
        bool u8 = (g_fa && g_fb);
        unsigned bits = 0;
        if (u8) {
            uint4 p0 = a[(size_t)t*2], p1 = a[(size_t)t*2 + 1];
            unsigned w[8] = {p0.x,p0.y,p0.z,p0.w,p1.x,p1.y,p1.z,p1.w};
            #pragma unroll
            for (int g = 0; g < 8; g++) {
                unsigned x = w[g];
                if (x & 0x000000FFu) bits |= 1u << (g*4+0);
                if (x & 0x0000FF00u) bits |= 1u << (g*4+1);
                if (x & 0x00FF0000u) bits |= 1u << (g*4+2);
                if (x & 0xFF000000u) bits |= 1u << (g*4+3);
            }
        } else {
            #pragma unroll
            for (int g = 0; g < 8; g++) {
                uint4 p = a[(size_t)t*8 + g];
                if (p.x) bits |= 1u << (g*4+0);
                if (p.y) bits |= 1u << (g*4+1);
                if (p.z) bits |= 1u << (g*4+2);
                if (p.w) bits |= 1u << (g*4+3);
            }
        }
        g_bits[t] = bits;
    } else if (blockIdx.x < PACK_BLOCKS + REC_BLOCKS) {
        int t = (blockIdx.x - PACK_BLOCKS) * blockDim.x + threadIdx.x;  // node
        float f[DD];
        #pragma unroll
        for (int d = 0; d < DD; d++) f[d] = feats[t*DD + d];
        float q[DD], k[DD], v[DD];
        #pragma unroll
        for (int e = 0; e < DD; e++) {
            float qq = 0.f, kk = 0.f, vv = 0.f;
            #pragma unroll
            for (int d = 0; d < DD; d++) {
                qq = fmaf(f[d], __ldg(&Wq[d*DD + e]), qq);
                kk = fmaf(f[d], __ldg(&Wk[d*DD + e]), kk);
                vv = fmaf(f[d], __ldg(&Wv[d*DD + e]), vv);
            }
            q[e] = qq; k[e] = kk; v[e] = vv;
        }
        #pragma unroll
        for (int e = 0; e < DD; e++)
            g_q[t*DD + e] = q[e] * 0.44721359549995793f;   // 1/sqrt(5)
        float c0 = coors[t*3+0], c1 = coors[t*3+1], c2 = coors[t*3+2];
        g_t0[t] = make_float4(k[0], k[1], k[2], k[3]);
        g_t1[t] = make_float4(c0, c1, c2, k[4]);
        g_t2[t] = make_float4(v[0], v[1], v[2], v[3]);
        g_t3[t] = v[4];
    } else if (threadIdx.x == 0) {
        // radial-MLP structure: with b1 == 0 (and dist > 0 always),
        // rbias(d) = d * sum_{h: w1_h>0} w1_h*w2_h + b2  -> single FMA.
        int simple = 1; float C = 0.f;
        #pragma unroll
        for (int h = 0; h < RH; h++) {
            float w1 = wr1[h];
            if (br1[h] != 0.f) simple = 0;
            if (w1 > 0.f) C = fmaf(w1, wr2[h], C);
        }
        g_simple = simple;
        g_C = C;
        g_bcShift = br2[0] - 30.0f;   // fixed softmax shift (scores bounded)
    }
}

// ---------------- 2-hop neighborhood + compaction (1 warp / row) -----------
__global__ void k_neigh() {
    int warp = (blockIdx.x * blockDim.x + threadIdx.x) >> 5;
    int lane = threadIdx.x & 31;
    if (warp >= ROWS) return;
    int b = warp / NN, i = warp % NN;

    unsigned self = g_bits[warp*NWORDS + lane];
    unsigned acc  = self;
    if ((i >> 5) == lane) acc |= 1u << (i & 31);     // eye

    int rowbase = b * NN;
    for (int w = 0; w < NWORDS; w++) {
        unsigned word = __shfl_sync(0xffffffffu, self, w);
        while (word) {
            int bit = __ffs(word) - 1; word &= word - 1;
            int j = w*32 + bit;
            acc |= g_bits[(rowbase + j)*NWORDS + lane];   // coalesced row OR
        }
    }
    // compact set bits -> index list
    int c = __popc(acc);
    int pre = c;
    #pragma unroll
    for (int off = 1; off < 32; off <<= 1) {
        int v = __shfl_up_sync(0xffffffffu, pre, off);
        if (lane >= off) pre += v;
    }
    int total = __shfl_sync(0xffffffffu, pre, 31);
    int pos = pre - c;
    unsigned m = acc;
    unsigned short* out = g_idx + (size_t)warp * NN;
    while (m) {
        int bit = __ffs(m) - 1; m &= m - 1;
        out[pos++] = (unsigned short)(lane*32 + bit);
    }
    if (lane == 0) g_cnt[warp] = total;
}

// ---------------- sparse attention, SMEM-staged gather ----------------------
// 32 CTAs per batch, 256 threads (8 warps), 4 rows per warp.
// Four flat smem tables (52KB): float4 tables give bank-group = j&7 -> full
// 8-way spread for random gathers. Shifted no-max softmax: e = exp(sc - 30).
__global__ void __launch_bounds__(256, 4)
k_attn(const float* __restrict__ feats,
       const float* __restrict__ Wo,
       const float* __restrict__ wr1,
       const float* __restrict__ br1,
       const float* __restrict__ wr2) {
    extern __shared__ float smemf[];
    float4* sT0 = (float4*)smemf;          // k0..k3
    float4* sT1 = sT0 + NN;                // cx,cy,cz,k4
    float4* sT2 = sT1 + NN;                // v0..v3
    float*  sT3 = (float*)(sT2 + NN);      // v4
    int b   = blockIdx.x >> 5;
    int seg = blockIdx.x & 31;

    {
        const float4* t0 = g_t0 + b*NN;
        const float4* t1 = g_t1 + b*NN;
        const float4* t2 = g_t2 + b*NN;
        const float*  t3 = g_t3 + b*NN;
        for (int i = threadIdx.x; i < NN; i += 256) {
            sT0[i] = t0[i]; sT1[i] = t1[i]; sT2[i] = t2[i]; sT3[i] = t3[i];
        }
    }
    __syncthreads();

    int lane = threadIdx.x & 31, warp = threadIdx.x >> 5;
    const int  simple  = g_simple;
    const float Cc     = g_C;
    const float bcS    = g_bcShift;

    #pragma unroll 1
    for (int r = 0; r < 4; r++) {
        int i   = seg * 32 + warp * 4 + r;    // row within batch
        int row = b * NN + i;

        float q0 = g_q[row*DD+0], q1 = g_q[row*DD+1], q2 = g_q[row*DD+2];
        float q3 = g_q[row*DD+3], q4 = g_q[row*DD+4];
        float4 ci = sT1[i];
        float cx = ci.x, cy = ci.y, cz = ci.z;

        int cnt = g_cnt[row];
        const unsigned short* idx = g_idx + (size_t)row * NN;

        float s = 0.f;
        float a0 = 0.f, a1 = 0.f, a2 = 0.f, a3 = 0.f, a4 = 0.f;

        for (int base = 0; base < cnt; base += 32) {
            int p = base + lane;
            if (p < cnt) {
                int j = (int)idx[p];
                float4 kk = sT0[j];
                float4 cj = sT1[j];
                float sc = bcS;
                sc = fmaf(q0, kk.x, sc); sc = fmaf(q1, kk.y, sc);
                sc = fmaf(q2, kk.z, sc); sc = fmaf(q3, kk.w, sc);
                sc = fmaf(q4, cj.w, sc);
                float dx = cx - cj.x, dy = cy - cj.y, dz = cz - cj.z;
                float d2 = fmaf(dx,dx, fmaf(dy,dy, fmaf(dz,dz, 1e-8f)));
                float dist = d2 * rsqrtf(d2);
                if (simple) {
                    sc = fmaf(dist, Cc, sc);
                } else {
                    #pragma unroll
                    for (int h = 0; h < RH; h++) {
                        float t = fmaf(dist, __ldg(&wr1[h]), __ldg(&br1[h]));
                        sc = fmaf(fmaxf(t, 0.f), __ldg(&wr2[h]), sc);
                    }
                }
                float e = __expf(sc);
                s += e;
                float4 vv = sT2[j];
                float  v4 = sT3[j];
                a0 = fmaf(e, vv.x, a0);
                a1 = fmaf(e, vv.y, a1);
                a2 = fmaf(e, vv.z, a2);
                a3 = fmaf(e, vv.w, a3);
                a4 = fmaf(e, v4,   a4);
            }
        }
        // plain-sum warp merge (common shift cancels in normalization)
        #pragma unroll
        for (int off = 16; off; off >>= 1) {
            s  += __shfl_xor_sync(0xffffffffu, s,  off);
            a0 += __shfl_xor_sync(0xffffffffu, a0, off);
            a1 += __shfl_xor_sync(0xffffffffu, a1, off);
            a2 += __shfl_xor_sync(0xffffffffu, a2, off);
            a3 += __shfl_xor_sync(0xffffffffu, a3, off);
            a4 += __shfl_xor_sync(0xffffffffu, a4, off);
        }
        if (lane == 0) {
            float inv = 1.f / s;
            float agg[DD] = {a0*inv, a1*inv, a2*inv, a3*inv, a4*inv};
            #pragma unroll
            for (int e = 0; e < DD; e++) {
                float o = feats[row*DD + e];
                #pragma unroll
                for (int d = 0; d < DD; d++) o = fmaf(agg[d], __ldg(&Wo[d*DD + e]), o);
                g_x[row*DD + e] = o;
            }
        }
    }
}

// ---------------- mean-pool + MLP head (1 block / batch) --------------------
__global__ void k_pool(const float* __restrict__ w1, const float* __restrict__ b1,
                       const float* __restrict__ w2, const float* __restrict__ b2,
                       float* __restrict__ out) {
    int b = blockIdx.x;
    int t = threadIdx.x;              // 256 threads
    __shared__ float red[DD*256];
    __shared__ float sp[DD];
    __shared__ float sh[128];

    float loc[DD] = {0.f,0.f,0.f,0.f,0.f};
    for (int i = t; i < NN; i += 256) {
        const float* x = g_x + (size_t)(b*NN + i)*DD;
        #pragma unroll
        for (int d = 0; d < DD; d++) loc[d] += x[d];
    }
    #pragma unroll
    for (int d = 0; d < DD; d++) red[d*256 + t] = loc[d];
    __syncthreads();
    if (t < DD) {
        float s = 0.f;
        for (int k = 0; k < 256; k++) s += red[t*256 + k];
        sp[t] = s * (1.0f/NN);
    }
    __syncthreads();
    if (t < 128) {
        float h = b1[t];
        #pragma unroll
        for (int d = 0; d < DD; d++) h = fmaf(sp[d], w1[d*128 + t], h);
        sh[t] = fmaxf(h, 0.f);
    }
    __syncthreads();
    if (t < 3) {
        float o = b2[t];
        for (int h = 0; h < 128; h++) o = fmaf(sh[h], w2[h*3 + t], o);
        out[b*3 + t] = o;
    }
}

// ---------------- launcher ---------------------------------------------------
extern "C" void kernel_launch(void* const* d_in, const int* in_sizes, int n_in,
                              void* d_out, int out_size) {
    const float* feats = (const float*)d_in[0];
    const float* coors = (const float*)d_in[1];
    const void*  adj   = d_in[2];
    const float* Wq    = (const float*)d_in[3];
    const float* Wk    = (const float*)d_in[4];
    const float* Wv    = (const float*)d_in[5];
    const float* Wo    = (const float*)d_in[6];
    const float* wr1   = (const float*)d_in[7];
    const float* br1   = (const float*)d_in[8];
    const float* wr2   = (const float*)d_in[9];
    const float* br2   = (const float*)d_in[10];
    const float* w1    = (const float*)d_in[11];
    const float* b1    = (const float*)d_in[12];
    const float* w2    = (const float*)d_in[13];
    const float* b2    = (const float*)d_in[14];
    float* out = (float*)d_out;

    const int ATTN_SMEM = (3*16 + 4) * 1024;   // 52KB
    cudaFuncSetAttribute(k_attn, cudaFuncAttributeMaxDynamicSharedMemorySize, ATTN_SMEM);

    k_detect<<<256, 256>>>((const uchar4*)adj, (4<<20)/4);
    k_pack_rec<<<PACK_BLOCKS + REC_BLOCKS + 1, 256>>>((const uint4*)adj, feats, coors,
                                                      Wq, Wk, Wv, wr1, br1, wr2, br2);
    k_neigh<<<(ROWS*32 + 255)/256, 256>>>();
    k_attn<<<BB*32, 256, ATTN_SMEM>>>(feats, Wo, wr1, br1, wr2);
    k_pool<<<BB, 256>>>(w1, b1, w2, b2, out);
}

// round 4
// speedup vs baseline: 2.2087x; 1.3476x over previous
#include <cuda_runtime.h>
#include <cuda_fp16.h>
#include <math.h>
#include <float.h>

#define BB 16
#define NN 1024
#define DD 5
#define RH 8
#define NWORDS 32            // 1024 bits / 32
#define ROWS (BB*NN)         // 16384
#define PACK_BLOCKS ((ROWS*NWORDS)/256)   // 2048
#define REC_BLOCKS  (ROWS/256)            // 64

// ---------------- scratch (static device globals; no runtime alloc) --------
__device__ unsigned int g_bits[ROWS*NWORDS];   // packed 1-hop adjacency (2 MB)
__device__ uint4        g_kv[ROWS];            // fp16: k0..k4, v0..v2 (8 halves)
__device__ float4       g_vc[ROWS];            // .x = half2(v3,v4), .y..w = coors
__device__ float        g_q[ROWS*DD];          // pre-scaled q
__device__ float        g_x[ROWS*DD];
__device__ int          g_fa, g_fb;            // dtype probe flags (zero-init, monotonic)
__device__ int          g_simple;              // rbias is linear in dist
__device__ float        g_C, g_bcShift;        // rbias slope, b2 - 30 shift

// ---------------- dtype probe ----------------------------------------------
// uint8 bools: nonzero bytes at all offsets  -> fa=1, fb=1
// int32 bools: nonzero only at offset%4==0   -> fa=1, fb=0
// f32   bools: 1.0f = 00 00 80 3f            -> fa=0, fb=1
__global__ void k_detect(const uchar4* __restrict__ a, int n4) {
    int t = blockIdx.x * blockDim.x + threadIdx.x;
    int stride = gridDim.x * blockDim.x;
    unsigned fa = 0, fb = 0;
    for (int i = t; i < n4; i += stride) {
        uchar4 u = a[i];
        fa |= u.x;
        fb |= (unsigned)(u.y | u.z | u.w);
    }
    if (fa) g_fa = 1;
    if (fb) g_fb = 1;
}

// ------- pack adjacency bitset + build node tables + radial coeffs ---------
__global__ void k_pack_rec(const uint4* __restrict__ a,
                           const float* __restrict__ feats,
                           const float* __restrict__ coors,
                           const float* __restrict__ Wq,
                           const float* __restrict__ Wk,
                           const float* __restrict__ Wv,
                           const float* __restrict__ wr1,
                           const float* __restrict__ br1,
                           const float* __restrict__ wr2,
                           const float* __restrict__ br2) {
    if (blockIdx.x < PACK_BLOCKS) {
        int t = blockIdx.x * blockDim.x + threadIdx.x;   // one 32-bit output word
        bool u8 = (g_fa && g_fb);
        unsigned bits = 0;
        if (u8) {
            uint4 p0 = a[(size_t)t*2], p1 = a[(size_t)t*2 + 1];
            unsigned w[8] = {p0.x,p0.y,p0.z,p0.w,p1.x,p1.y,p1.z,p1.w};
            #pragma unroll
            for (int g = 0; g < 8; g++) {
                unsigned x = w[g];
                if (x & 0x000000FFu) bits |= 1u << (g*4+0);
                if (x & 0x0000FF00u) bits |= 1u << (g*4+1);
                if (x & 0x00FF0000u) bits |= 1u << (g*4+2);
                if (x & 0xFF000000u) bits |= 1u << (g*4+3);
            }
        } else {
            #pragma unroll
            for (int g = 0; g < 8; g++) {
                uint4 p = a[(size_t)t*8 + g];
                if (p.x) bits |= 1u << (g*4+0);
                if (p.y) bits |= 1u << (g*4+1);
                if (p.z) bits |= 1u << (g*4+2);
                if (p.w) bits |= 1u << (g*4+3);
            }
        }
        g_bits[t] = bits;
    } else if (blockIdx.x < PACK_BLOCKS + REC_BLOCKS) {
        int t = (blockIdx.x - PACK_BLOCKS) * blockDim.x + threadIdx.x;  // node
        float f[DD];
        #pragma unroll
        for (int d = 0; d < DD; d++) f[d] = feats[t*DD + d];
        float q[DD], k[DD], v[DD];
        #pragma unroll
        for (int e = 0; e < DD; e++) {
            float qq = 0.f, kk = 0.f, vv = 0.f;
            #pragma unroll
            for (int d = 0; d < DD; d++) {
                qq = fmaf(f[d], __ldg(&Wq[d*DD + e]), qq);
                kk = fmaf(f[d], __ldg(&Wk[d*DD + e]), kk);
                vv = fmaf(f[d], __ldg(&Wv[d*DD + e]), vv);
            }
            q[e] = qq; k[e] = kk; v[e] = vv;
        }
        #pragma unroll
        for (int e = 0; e < DD; e++)
            g_q[t*DD + e] = q[e] * 0.44721359549995793f;   // 1/sqrt(5)
        float c0 = coors[t*3+0], c1 = coors[t*3+1], c2 = coors[t*3+2];
        half2 p01 = __floats2half2_rn(k[0], k[1]);
        half2 p23 = __floats2half2_rn(k[2], k[3]);
        half2 p45 = __floats2half2_rn(k[4], v[0]);
        half2 p67 = __floats2half2_rn(v[1], v[2]);
        uint4 kv;
        kv.x = *(unsigned*)&p01; kv.y = *(unsigned*)&p23;
        kv.z = *(unsigned*)&p45; kv.w = *(unsigned*)&p67;
        g_kv[t] = kv;
        half2 p89 = __floats2half2_rn(v[3], v[4]);
        float4 vc;
        vc.x = *(float*)&p89; vc.y = c0; vc.z = c1; vc.w = c2;
        g_vc[t] = vc;
    } else if (threadIdx.x == 0) {
        // radial-MLP structure: with b1 == 0 (and dist > 0 always),
        // rbias(d) = d * sum_{h: w1_h>0} w1_h*w2_h + b2  -> single FMA.
        int simple = 1; float C = 0.f;
        #pragma unroll
        for (int h = 0; h < RH; h++) {
            float w1 = wr1[h];
            if (br1[h] != 0.f) simple = 0;
            if (w1 > 0.f) C = fmaf(w1, wr2[h], C);
        }
        g_simple = simple;
        g_C = C;
        g_bcShift = br2[0] - 30.0f;   // fixed softmax shift (scores bounded)
    }
}

// ------ fused 2-hop neighborhood + sparse attention --------------------------
// 32 CTAs per batch, 256 threads (8 warps), 4 rows per warp.
// Per-batch fp16 kv table + fp32 coor table in smem (32KB, 16B-stride ->
// full 8-way bank-group spread). Each warp builds its row's 2-hop index list
// in a per-warp smem buffer (no global round-trip), then gathers.
// Shifted no-max softmax: e = exp(sc - 30), shift cancels in normalization.
__global__ void __launch_bounds__(256, 4)
k_attn(const float* __restrict__ feats,
       const float* __restrict__ Wo,
       const float* __restrict__ wr1,
       const float* __restrict__ br1,
       const float* __restrict__ wr2) {
    extern __shared__ float smemf[];
    uint4*  sKV = (uint4*)smemf;                       // 16KB
    float4* sVC = (float4*)(sKV + NN);                 // 16KB
    unsigned short* sIdx = (unsigned short*)(sVC + NN);// 8 warps * 1024 * 2B = 16KB
    int b   = blockIdx.x >> 5;
    int seg = blockIdx.x & 31;

    {
        const uint4*  t0 = g_kv + b*NN;
        const float4* t1 = g_vc + b*NN;
        for (int i = threadIdx.x; i < NN; i += 256) {
            sKV[i] = t0[i]; sVC[i] = t1[i];
        }
    }
    __syncthreads();

    int lane = threadIdx.x & 31, warp = threadIdx.x >> 5;
    unsigned short* widx = sIdx + warp * NN;
    const int   simple = g_simple;
    const float Cc     = g_C;
    const float bcS    = g_bcShift;
    const unsigned FULL = 0xffffffffu;

    #pragma unroll 1
    for (int r = 0; r < 4; r++) {
        int i   = seg * 32 + warp * 4 + r;    // row within batch
        int row = b * NN + i;

        // ---- 2-hop bitset for this row (lane owns word `lane`) ----
        const unsigned* bb = g_bits + (size_t)(b*NN)*NWORDS;
        unsigned self = bb[(size_t)i*NWORDS + lane];
        unsigned acc  = self;
        if ((i >> 5) == lane) acc |= 1u << (i & 31);     // eye
        #pragma unroll 1
        for (int w = 0; w < NWORDS; w++) {
            unsigned word = __shfl_sync(FULL, self, w);
            while (word) {
                int bit = __ffs(word) - 1; word &= word - 1;
                acc |= bb[(size_t)(w*32 + bit)*NWORDS + lane];
            }
        }
        // ---- compact bits -> per-warp smem index list ----
        int c = __popc(acc);
        int pre = c;
        #pragma unroll
        for (int off = 1; off < 32; off <<= 1) {
            int vsh = __shfl_up_sync(FULL, pre, off);
            if (lane >= off) pre += vsh;
        }
        int cnt = __shfl_sync(FULL, pre, 31);
        int pos = pre - c;
        unsigned mm = acc;
        while (mm) {
            int bit = __ffs(mm) - 1; mm &= mm - 1;
            widx[pos++] = (unsigned short)(lane*32 + bit);
        }
        __syncwarp(FULL);

        // ---- gather + softmax-weighted aggregate ----
        float q0 = g_q[row*DD+0], q1 = g_q[row*DD+1], q2 = g_q[row*DD+2];
        float q3 = g_q[row*DD+3], q4 = g_q[row*DD+4];
        float4 ci = sVC[i];
        float cx = ci.y, cy = ci.z, cz = ci.w;

        float s = 0.f;
        float a0 = 0.f, a1 = 0.f, a2 = 0.f, a3 = 0.f, a4 = 0.f;

        for (int base = 0; base < cnt; base += 32) {
            int p = base + lane;
            if (p < cnt) {
                int j = (int)widx[p];
                uint4  kv = sKV[j];
                float4 vc = sVC[j];
                float2 k01 = __half22float2(*(half2*)&kv.x);
                float2 k23 = __half22float2(*(half2*)&kv.y);
                float2 k4v0 = __half22float2(*(half2*)&kv.z);
                float2 v12 = __half22float2(*(half2*)&kv.w);
                float2 v34 = __half22float2(*(half2*)&vc.x);

                float sc = bcS;
                sc = fmaf(q0, k01.x, sc); sc = fmaf(q1, k01.y, sc);
                sc = fmaf(q2, k23.x, sc); sc = fmaf(q3, k23.y, sc);
                sc = fmaf(q4, k4v0.x, sc);
                float dx = cx - vc.y, dy = cy - vc.z, dz = cz - vc.w;
                float d2 = fmaf(dx,dx, fmaf(dy,dy, fmaf(dz,dz, 1e-8f)));
                float dist = d2 * rsqrtf(d2);
                if (simple) {
                    sc = fmaf(dist, Cc, sc);
                } else {
                    #pragma unroll
                    for (int h = 0; h < RH; h++) {
                        float t = fmaf(dist, __ldg(&wr1[h]), __ldg(&br1[h]));
                        sc = fmaf(fmaxf(t, 0.f), __ldg(&wr2[h]), sc);
                    }
                }
                float e = __expf(sc);
                s += e;
                a0 = fmaf(e, k4v0.y, a0);
                a1 = fmaf(e, v12.x,  a1);
                a2 = fmaf(e, v12.y,  a2);
                a3 = fmaf(e, v34.x,  a3);
                a4 = fmaf(e, v34.y,  a4);
            }
        }
        // plain-sum warp merge (common shift cancels in normalization)
        #pragma unroll
        for (int off = 16; off; off >>= 1) {
            s  += __shfl_xor_sync(FULL, s,  off);
            a0 += __shfl_xor_sync(FULL, a0, off);
            a1 += __shfl_xor_sync(FULL, a1, off);
            a2 += __shfl_xor_sync(FULL, a2, off);
            a3 += __shfl_xor_sync(FULL, a3, off);
            a4 += __shfl_xor_sync(FULL, a4, off);
        }
        if (lane == 0) {
            float inv = 1.f / s;
            float agg[DD] = {a0*inv, a1*inv, a2*inv, a3*inv, a4*inv};
            #pragma unroll
            for (int e = 0; e < DD; e++) {
                float o = feats[row*DD + e];
                #pragma unroll
                for (int d = 0; d < DD; d++) o = fmaf(agg[d], __ldg(&Wo[d*DD + e]), o);
                g_x[row*DD + e] = o;
            }
        }
        __syncwarp(FULL);
    }
}

// ---------------- mean-pool + MLP head (1 block / batch) --------------------
__global__ void k_pool(const float* __restrict__ w1, const float* __restrict__ b1,
                       const float* __restrict__ w2, const float* __restrict__ b2,
                       float* __restrict__ out) {
    int b = blockIdx.x;
    int t = threadIdx.x;              // 256 threads
    __shared__ float red[DD*256];
    __shared__ float sp[DD];
    __shared__ float sh[128];

    float loc[DD] = {0.f,0.f,0.f,0.f,0.f};
    for (int i = t; i < NN; i += 256) {
        const float* x = g_x + (size_t)(b*NN + i)*DD;
        #pragma unroll
        for (int d = 0; d < DD; d++) loc[d] += x[d];
    }
    #pragma unroll
    for (int d = 0; d < DD; d++) red[d*256 + t] = loc[d];
    __syncthreads();
    if (t < DD) {
        float s = 0.f;
        for (int k = 0; k < 256; k++) s += red[t*256 + k];
        sp[t] = s * (1.0f/NN);
    }
    __syncthreads();
    if (t < 128) {
        float h = b1[t];
        #pragma unroll
        for (int d = 0; d < DD; d++) h = fmaf(sp[d], w1[d*128 + t], h);
        sh[t] = fmaxf(h, 0.f);
    }
    __syncthreads();
    if (t < 3) {
        float o = b2[t];
        for (int h = 0; h < 128; h++) o = fmaf(sh[h], w2[h*3 + t], o);
        out[b*3 + t] = o;
    }
}

// ---------------- launcher ---------------------------------------------------
extern "C" void kernel_launch(void* const* d_in, const int* in_sizes, int n_in,
                              void* d_out, int out_size) {
    const float* feats = (const float*)d_in[0];
    const float* coors = (const float*)d_in[1];
    const void*  adj   = d_in[2];
    const float* Wq    = (const float*)d_in[3];
    const float* Wk    = (const float*)d_in[4];
    const float* Wv    = (const float*)d_in[5];
    const float* Wo    = (const float*)d_in[6];
    const float* wr1   = (const float*)d_in[7];
    const float* br1   = (const float*)d_in[8];
    const float* wr2   = (const float*)d_in[9];
    const float* br2   = (const float*)d_in[10];
    const float* w1    = (const float*)d_in[11];
    const float* b1    = (const float*)d_in[12];
    const float* w2    = (const float*)d_in[13];
    const float* b2    = (const float*)d_in[14];
    float* out = (float*)d_out;

    const int ATTN_SMEM = 48 * 1024;   // 16 kv + 16 vc + 16 idx
    cudaFuncSetAttribute(k_attn, cudaFuncAttributeMaxDynamicSharedMemorySize, ATTN_SMEM);

    k_detect<<<256, 256>>>((const uchar4*)adj, (4<<20)/4);
    k_pack_rec<<<PACK_BLOCKS + REC_BLOCKS + 1, 256>>>((const uint4*)adj, feats, coors,
                                                      Wq, Wk, Wv, wr1, br1, wr2, br2);
    k_attn<<<BB*32, 256, ATTN_SMEM>>>(feats, Wo, wr1, br1, wr2);
    k_pool<<<BB, 256>>>(w1, b1, w2, b2, out);
}

// round 5
// speedup vs baseline: 2.2664x; 1.0261x over previous
#include <cuda_runtime.h>
#include <cuda_fp16.h>
#include <math.h>
#include <float.h>

#define BB 16
#define NN 1024
#define DD 5
#define RH 8
#define NWORDS 32            // 1024 bits / 32
#define ROWS (BB*NN)         // 16384
#define PACK_BLOCKS ((ROWS*NWORDS)/256)   // 2048
#define REC_BLOCKS  (ROWS/256)            // 64
#define LOG2E 1.4426950408889634f

// ---------------- scratch (static device globals; no runtime alloc) --------
__device__ unsigned int g_bits[ROWS*NWORDS];   // packed 1-hop adjacency (2 MB)
__device__ uint4        g_kv[ROWS];            // fp16: (k0,k1)(k2,k3)(k4,v0)(v1,v2)
__device__ float4       g_vc[ROWS];            // .x = half2(v3,v4), .y..w = coors
__device__ float4       g_q4[ROWS];            // q0..q3, pre-scaled by log2e/sqrt(5)
__device__ float        g_q1[ROWS];            // q4, same scale
__device__ float        g_part[BB*32*DD];      // per-CTA agg partial sums
__device__ int          g_simple;              // rbias is linear in dist
__device__ float        g_C, g_bcShift;        // log2e-scaled slope / shifted bias

// ------- pack adjacency bitset + build node tables + radial coeffs ---------
// dtype probe (per pack block, first 8KB):
//   uint8 bools: nonzero at all byte offsets       -> fa=1, fb=1
//   int32 bools: nonzero only at offset%4==0       -> fa=1, fb=0
//   f32   bools: 1.0f bytes at offsets 2,3         -> fa=0, fb=1
__global__ void k_pack_rec(const uint4* __restrict__ a,
                           const float* __restrict__ feats,
                           const float* __restrict__ coors,
                           const float* __restrict__ Wq,
                           const float* __restrict__ Wk,
                           const float* __restrict__ Wv,
                           const float* __restrict__ wr1,
                           const float* __restrict__ br1,
                           const float* __restrict__ wr2,
                           const float* __restrict__ br2) {
    if (blockIdx.x < PACK_BLOCKS) {
        __shared__ unsigned sFa, sFb;
        if (threadIdx.x == 0) { sFa = 0; sFb = 0; }
        __syncthreads();
        {
            const uchar4* p8 = (const uchar4*)a;
            unsigned fa = 0, fb = 0;
            #pragma unroll
            for (int k = 0; k < 8; k++) {
                uchar4 u = p8[threadIdx.x + k*256];
                fa |= u.x;
                fb |= (unsigned)(u.y | u.z | u.w);
            }
            if (fa) atomicOr(&sFa, 1u);
            if (fb) atomicOr(&sFb, 1u);
        }
        __syncthreads();
        bool u8 = sFa && sFb;

        int t = blockIdx.x * blockDim.x + threadIdx.x;   // one 32-bit output word
        unsigned bits = 0;
        if (u8) {
            uint4 p0 = a[(size_t)t*2], p1 = a[(size_t)t*2 + 1];
            unsigned w[8] = {p0.x,p0.y,p0.z,p0.w,p1.x,p1.y,p1.z,p1.w};
            #pragma unroll
            for (int g = 0; g < 8; g++) {
                unsigned x = w[g];
                if (x & 0x000000FFu) bits |= 1u << (g*4+0);
                if (x & 0x0000FF00u) bits |= 1u << (g*4+1);
                if (x & 0x00FF0000u) bits |= 1u << (g*4+2);
                if (x & 0xFF000000u) bits |= 1u << (g*4+3);
            }
        } else {
            #pragma unroll
            for (int g = 0; g < 8; g++) {
                uint4 p = a[(size_t)t*8 + g];
                if (p.x) bits |= 1u << (g*4+0);
                if (p.y) bits |= 1u << (g*4+1);
                if (p.z) bits |= 1u << (g*4+2);
                if (p.w) bits |= 1u << (g*4+3);
            }
        }
        g_bits[t] = bits;
    } else if (blockIdx.x < PACK_BLOCKS + REC_BLOCKS) {
        int t = (blockIdx.x - PACK_BLOCKS) * blockDim.x + threadIdx.x;  // node
        float f[DD];
        #pragma unroll
        for (int d = 0; d < DD; d++) f[d] = feats[t*DD + d];
        float q[DD], k[DD], v[DD];
        #pragma unroll
        for (int e = 0; e < DD; e++) {
            float qq = 0.f, kk = 0.f, vv = 0.f;
            #pragma unroll
            for (int d = 0; d < DD; d++) {
                qq = fmaf(f[d], __ldg(&Wq[d*DD + e]), qq);
                kk = fmaf(f[d], __ldg(&Wk[d*DD + e]), kk);
                vv = fmaf(f[d], __ldg(&Wv[d*DD + e]), vv);
            }
            q[e] = qq; k[e] = kk; v[e] = vv;
        }
        const float qs = 0.44721359549995793f * LOG2E;  // log2e/sqrt(5)
        g_q4[t] = make_float4(q[0]*qs, q[1]*qs, q[2]*qs, q[3]*qs);
        g_q1[t] = q[4]*qs;
        float c0 = coors[t*3+0], c1 = coors[t*3+1], c2 = coors[t*3+2];
        half2 p01 = __floats2half2_rn(k[0], k[1]);
        half2 p23 = __floats2half2_rn(k[2], k[3]);
        half2 p45 = __floats2half2_rn(k[4], v[0]);
        half2 p67 = __floats2half2_rn(v[1], v[2]);
        uint4 kv;
        kv.x = *(unsigned*)&p01; kv.y = *(unsigned*)&p23;
        kv.z = *(unsigned*)&p45; kv.w = *(unsigned*)&p67;
        g_kv[t] = kv;
        half2 p89 = __floats2half2_rn(v[3], v[4]);
        float4 vc;
        vc.x = *(float*)&p89; vc.y = c0; vc.z = c1; vc.w = c2;
        g_vc[t] = vc;
    } else if (threadIdx.x == 0) {
        // radial-MLP structure: with b1 == 0 (and dist > 0 always),
        // rbias(d) = d * sum_{h: w1_h>0} w1_h*w2_h + b2  -> single FMA.
        int simple = 1; float C = 0.f;
        #pragma unroll
        for (int h = 0; h < RH; h++) {
            float w1 = wr1[h];
            if (br1[h] != 0.f) simple = 0;
            if (w1 > 0.f) C = fmaf(w1, wr2[h], C);
        }
        g_simple = simple;
        g_C = C * LOG2E;
        g_bcShift = (br2[0] - 30.0f) * LOG2E;  // fixed softmax shift (scores bounded)
    }
}

__device__ __forceinline__ float ex2f(float x) {
    float y; asm("ex2.approx.f32 %0, %1;" : "=f"(y) : "f"(x)); return y;
}
__device__ __forceinline__ float sqrtapx(float x) {
    float y; asm("sqrt.approx.f32 %0, %1;" : "=f"(y) : "f"(x)); return y;
}

// ------ fused 2-hop neighborhood + sparse attention + CTA pooling -----------
// 32 CTAs per batch, 256 threads (8 warps), 4 rows per warp.
// Per-batch fp16 kv + fp32 coor tables in smem (32KB, 16B stride -> 8-way
// bank-group spread). Warp builds its row's 2-hop index list in per-warp smem,
// gathers with shifted no-max softmax e = ex2(log2e*(sc-30)); shift cancels.
// CTA reduces its 32 rows' normalized agg in fixed order -> g_part (no Wo,
// no per-row global writes).
__global__ void __launch_bounds__(256, 4)
k_attn(const float* __restrict__ wr1,
       const float* __restrict__ br1,
       const float* __restrict__ wr2) {
    extern __shared__ float smemf[];
    uint4*  sKV = (uint4*)smemf;                       // 16KB
    float4* sVC = (float4*)(sKV + NN);                 // 16KB
    unsigned short* sIdx = (unsigned short*)(sVC + NN);// 16KB
    float* sAgg = (float*)(sIdx + 8*NN);               // 32*5 = 640B
    int b   = blockIdx.x >> 5;
    int seg = blockIdx.x & 31;

    {
        const uint4*  t0 = g_kv + b*NN;
        const float4* t1 = g_vc + b*NN;
        for (int i = threadIdx.x; i < NN; i += 256) {
            sKV[i] = t0[i]; sVC[i] = t1[i];
        }
    }
    __syncthreads();

    int lane = threadIdx.x & 31, warp = threadIdx.x >> 5;
    unsigned short* widx = sIdx + warp * NN;
    const int   simple = g_simple;
    const float Cc     = g_C;
    const float bcS    = g_bcShift;
    const unsigned FULL = 0xffffffffu;

    #pragma unroll 1
    for (int r = 0; r < 4; r++) {
        int i   = seg * 32 + warp * 4 + r;    // row within batch
        int row = b * NN + i;

        // ---- 2-hop bitset for this row (lane owns word `lane`) ----
        const unsigned* bb = g_bits + (size_t)(b*NN)*NWORDS;
        unsigned self = bb[(size_t)i*NWORDS + lane];
        unsigned acc  = self;
        if ((i >> 5) == lane) acc |= 1u << (i & 31);     // eye
        #pragma unroll 1
        for (int w = 0; w < NWORDS; w++) {
            unsigned word = __shfl_sync(FULL, self, w);
            while (word) {
                int bit = __ffs(word) - 1; word &= word - 1;
                acc |= bb[(size_t)(w*32 + bit)*NWORDS + lane];
            }
        }
        // ---- compact bits -> per-warp smem index list ----
        int c = __popc(acc);
        int pre = c;
        #pragma unroll
        for (int off = 1; off < 32; off <<= 1) {
            int vsh = __shfl_up_sync(FULL, pre, off);
            if (lane >= off) pre += vsh;
        }
        int cnt = __shfl_sync(FULL, pre, 31);
        int pos = pre - c;
        unsigned mm = acc;
        while (mm) {
            int bit = __ffs(mm) - 1; mm &= mm - 1;
            widx[pos++] = (unsigned short)(lane*32 + bit);
        }
        __syncwarp(FULL);

        // ---- gather + softmax-weighted aggregate ----
        float4 qv = g_q4[row];
        float  q4 = g_q1[row];
        float4 ci = sVC[i];
        float cx = ci.y, cy = ci.z, cz = ci.w;

        float s = 0.f;
        float a0 = 0.f, a1 = 0.f, a2 = 0.f, a3 = 0.f, a4 = 0.f;

        for (int base = 0; base < cnt; base += 32) {
            int p = base + lane;
            if (p < cnt) {
                int j = (int)widx[p];
                uint4  kv = sKV[j];
                float4 vc = sVC[j];
                float2 k01  = __half22float2(*(half2*)&kv.x);
                float2 k23  = __half22float2(*(half2*)&kv.y);
                float2 k4v0 = __half22float2(*(half2*)&kv.z);
                float2 v12  = __half22float2(*(half2*)&kv.w);
                float2 v34  = __half22float2(*(half2*)&vc.x);

                float sc = bcS;
                sc = fmaf(qv.x, k01.x, sc); sc = fmaf(qv.y, k01.y, sc);
                sc = fmaf(qv.z, k23.x, sc); sc = fmaf(qv.w, k23.y, sc);
                sc = fmaf(q4, k4v0.x, sc);
                float dx = cx - vc.y, dy = cy - vc.z, dz = cz - vc.w;
                float d2 = fmaf(dx,dx, fmaf(dy,dy, fmaf(dz,dz, 1e-8f)));
                float dist = sqrtapx(d2);
                if (simple) {
                    sc = fmaf(dist, Cc, sc);
                } else {
                    float rb = 0.f;
                    #pragma unroll
                    for (int h = 0; h < RH; h++) {
                        float t = fmaf(dist, __ldg(&wr1[h]), __ldg(&br1[h]));
                        rb = fmaf(fmaxf(t, 0.f), __ldg(&wr2[h]), rb);
                    }
                    sc = fmaf(rb, LOG2E, sc);
                }
                float e = ex2f(sc);
                s += e;
                a0 = fmaf(e, k4v0.y, a0);
                a1 = fmaf(e, v12.x,  a1);
                a2 = fmaf(e, v12.y,  a2);
                a3 = fmaf(e, v34.x,  a3);
                a4 = fmaf(e, v34.y,  a4);
            }
        }
        // plain-sum warp merge (common shift cancels in normalization)
        #pragma unroll
        for (int off = 16; off; off >>= 1) {
            s  += __shfl_xor_sync(FULL, s,  off);
            a0 += __shfl_xor_sync(FULL, a0, off);
            a1 += __shfl_xor_sync(FULL, a1, off);
            a2 += __shfl_xor_sync(FULL, a2, off);
            a3 += __shfl_xor_sync(FULL, a3, off);
            a4 += __shfl_xor_sync(FULL, a4, off);
        }
        if (lane == 0) {
            float inv = 1.f / s;
            float* dst = sAgg + (warp*4 + r)*DD;
            dst[0] = a0*inv; dst[1] = a1*inv; dst[2] = a2*inv;
            dst[3] = a3*inv; dst[4] = a4*inv;
        }
        __syncwarp(FULL);
    }
    __syncthreads();
    if (threadIdx.x < DD) {
        float t = 0.f;
        #pragma unroll 1
        for (int rr = 0; rr < 32; rr++) t += sAgg[rr*DD + threadIdx.x];
        g_part[blockIdx.x*DD + threadIdx.x] = t;   // fixed order -> deterministic
    }
}

// ---------------- head: pool feats + agg partials, Wo, MLP ------------------
__global__ void k_head(const float* __restrict__ feats,
                       const float* __restrict__ Wo,
                       const float* __restrict__ w1, const float* __restrict__ b1,
                       const float* __restrict__ w2, const float* __restrict__ b2,
                       float* __restrict__ out) {
    int b = blockIdx.x;
    int t = threadIdx.x;              // 256 threads
    int lane = t & 31, warp = t >> 5;
    __shared__ float wsF[8][DD];
    __shared__ float spF[DD], spA[DD], sp[DD];
    __shared__ float sh[128];

    float lf[DD] = {0.f,0.f,0.f,0.f,0.f};
    for (int i = t; i < NN; i += 256) {
        const float* f = feats + ((size_t)b*NN + i)*DD;
        #pragma unroll
        for (int d = 0; d < DD; d++) lf[d] += f[d];
    }
    float la[DD] = {0.f,0.f,0.f,0.f,0.f};
    if (t < 32) {
        const float* p = g_part + (b*32 + t)*DD;
        #pragma unroll
        for (int d = 0; d < DD; d++) la[d] = p[d];
    }
    #pragma unroll
    for (int off = 16; off; off >>= 1) {
        #pragma unroll
        for (int d = 0; d < DD; d++) {
            lf[d] += __shfl_xor_sync(0xffffffffu, lf[d], off);
            la[d] += __shfl_xor_sync(0xffffffffu, la[d], off);
        }
    }
    if (lane == 0) {
        #pragma unroll
        for (int d = 0; d < DD; d++) wsF[warp][d] = lf[d];
        if (warp == 0) {
            #pragma unroll
            for (int d = 0; d < DD; d++) spA[d] = la[d] * (1.0f/NN);
        }
    }
    __syncthreads();
    if (t < DD) {
        float s = 0.f;
        #pragma unroll
        for (int w = 0; w < 8; w++) s += wsF[w][t];
        spF[t] = s * (1.0f/NN);
    }
    __syncthreads();
    if (t < DD) {
        float o = spF[t];
        #pragma unroll
        for (int d = 0; d < DD; d++) o = fmaf(spA[d], __ldg(&Wo[d*DD + t]), o);
        sp[t] = o;
    }
    __syncthreads();
    if (t < 128) {
        float h = b1[t];
        #pragma unroll
        for (int d = 0; d < DD; d++) h = fmaf(sp[d], w1[d*128 + t], h);
        sh[t] = fmaxf(h, 0.f);
    }
    __syncthreads();
    if (t < 3) {
        float o = b2[t];
        for (int h = 0; h < 128; h++) o = fmaf(sh[h], w2[h*3 + t], o);
        out[b*3 + t] = o;
    }
}

// ---------------- launcher ---------------------------------------------------
extern "C" void kernel_launch(void* const* d_in, const int* in_sizes, int n_in,
                              void* d_out, int out_size) {
    const float* feats = (const float*)d_in[0];
    const float* coors = (const float*)d_in[1];
    const void*  adj   = d_in[2];
    const float* Wq    = (const float*)d_in[3];
    const float* Wk    = (const float*)d_in[4];
    const float* Wv    = (const float*)d_in[5];
    const float* Wo    = (const float*)d_in[6];
    const float* wr1   = (const float*)d_in[7];
    const float* br1   = (const float*)d_in[8];
    const float* wr2   = (const float*)d_in[9];
    const float* br2   = (const float*)d_in[10];
    const float* w1    = (const float*)d_in[11];
    const float* b1    = (const float*)d_in[12];
    const float* w2    = (const float*)d_in[13];
    const float* b2    = (const float*)d_in[14];
    float* out = (float*)d_out;

    const int ATTN_SMEM = 48*1024 + 32*DD*4;   // tables + idx + agg
    cudaFuncSetAttribute(k_attn, cudaFuncAttributeMaxDynamicSharedMemorySize, ATTN_SMEM);

    k_pack_rec<<<PACK_BLOCKS + REC_BLOCKS + 1, 256>>>((const uint4*)adj, feats, coors,
                                                      Wq, Wk, Wv, wr1, br1, wr2, br2);
    k_attn<<<BB*32, 256, ATTN_SMEM>>>(wr1, br1, wr2);
    k_head<<<BB, 256>>>(feats, Wo, w1, b1, w2, b2, out);
}